// round 14
// baseline (speedup 1.0000x reference)
#include <cuda_runtime.h>
#include <cuda_fp16.h>
#include <cstdint>

#define NN   2048
#define NE   4096
#define NG   32
#define AD   79
#define BD   12
#define DD   128
#define NL   6
#define NT   6
#define KKD  16512          // 128*128 + 128 bias rows
#define EMAX 96
#define HSPL 16             // split-K CTAs: 1032 stages of 16 (first 8 CTAs take 65, rest 64)

typedef unsigned long long ull;
typedef unsigned int uint32;

// ------------- static scratch (no allocations allowed) -------------
__device__ float  g_h[NN * DD];
__device__ float  g_t[NE * DD];
__device__ __half g_Sh[(size_t)NN * KKD];             // 67.5 MB fp16-hi
__device__ __half g_Sl[(size_t)NN * KKD];             // 67.5 MB fp16-lo (x2048)
__device__ __half g_W2h[(size_t)NL * 129 * 16384];    // 25.4 MB
__device__ __half g_W2l[(size_t)NL * 129 * 16384];    // 25.4 MB (x2048)
__device__ float  g_part[(size_t)HSPL * NN * DD];     // 16 MB (L2-resident)
__device__ float  g_gi[NN * 384];
__device__ float  g_gh[NN * 384];
__device__ float  g_WihT[NL * 128 * 384];
__device__ float  g_WhhT[NL * 128 * 384];
__device__ float  g_lWihT[128 * 512];
__device__ float  g_lWhhT[128 * 512];
__device__ int    g_src[NE], g_dst[NE];
__device__ int    g_eidx[NN * EMAX];
__device__ int    g_cnt[NN];

// ------------- helpers -------------
__device__ __forceinline__ float gelu_f(float x) {
    return 0.5f * x * (1.0f + erff(x * 0.70710678f));
}
__device__ __forceinline__ float sigm(float x) { return 1.0f / (1.0f + expf(-x)); }

__device__ __forceinline__ ull pk2(float lo, float hi) {
    ull r; asm("mov.b64 %0, {%1, %2};" : "=l"(r) : "f"(lo), "f"(hi)); return r;
}
__device__ __forceinline__ void upk2(ull v, float& lo, float& hi) {
    asm("mov.b64 {%0, %1}, %2;" : "=f"(lo), "=f"(hi) : "l"(v));
}
__device__ __forceinline__ void ffma2(ull& d, ull a, ull b) {
    asm("fma.rn.f32x2 %0, %1, %2, %0;" : "+l"(d) : "l"(a), "l"(b));
}

// fp16 m16n8k16 mma, fp32 accumulate
__device__ __forceinline__ void mma_f16(float* c, const uint32* a, const uint32* b) {
    asm volatile(
        "mma.sync.aligned.m16n8k16.row.col.f32.f16.f16.f32 "
        "{%0,%1,%2,%3}, {%4,%5,%6,%7}, {%8,%9}, {%0,%1,%2,%3};\n"
        : "+f"(c[0]), "+f"(c[1]), "+f"(c[2]), "+f"(c[3])
        : "r"(a[0]), "r"(a[1]), "r"(a[2]), "r"(a[3]), "r"(b[0]), "r"(b[1]));
}

__device__ __forceinline__ void ldm_x4(uint32& r0, uint32& r1, uint32& r2, uint32& r3,
                                       uint32 addr) {
    asm volatile("ldmatrix.sync.aligned.m8n8.x4.shared.b16 {%0,%1,%2,%3}, [%4];"
                 : "=r"(r0), "=r"(r1), "=r"(r2), "=r"(r3) : "r"(addr));
}

__device__ __forceinline__ uint32 smem_u32(const void* p) {
    uint32 a;
    asm("{ .reg .u64 t; cvta.to.shared.u64 t, %1; cvt.u32.u64 %0, t; }" : "=r"(a) : "l"(p));
    return a;
}

__device__ __forceinline__ float bsum128(float v, float* red) {
    #pragma unroll
    for (int o = 16; o > 0; o >>= 1) v += __shfl_down_sync(0xffffffffu, v, o);
    if ((threadIdx.x & 31) == 0) red[threadIdx.x >> 5] = v;
    __syncthreads();
    float r = red[0] + red[1] + red[2] + red[3];
    __syncthreads();
    return r;
}

// split v into fp16 hi + fp16 lo*2048
__device__ __forceinline__ void hsplit(float v, __half& h, __half& l) {
    h = __float2half_rn(v);
    l = __float2half_rn((v - __half2float(h)) * 2048.0f);
}

// ------------- prep -------------
__global__ void k_prep(const int* __restrict__ ei) {
    int n = blockIdx.x, t = threadIdx.x;
    bool my64 = true;
    for (int i = t; i < 128; i += 32)
        if (ei[2 * i + 1] != 0) my64 = false;
    bool is64 = __all_sync(0xffffffffu, my64);
    if (t < 2) {
        int e = n * 2 + t;
        g_src[e] = is64 ? ei[2 * e]        : ei[e];
        g_dst[e] = is64 ? ei[2 * (NE + e)] : ei[NE + e];
    }
    int cnt = 0;
    for (int base = 0; base < NE; base += 32) {
        int e = base + t;
        int dv = is64 ? ei[2 * (NE + e)] : ei[NE + e];
        bool ok = (dv == n);
        unsigned m = __ballot_sync(0xffffffffu, ok);
        if (ok) {
            int pos = cnt + __popc(m & ((1u << t) - 1u));
            if (pos < EMAX) g_eidx[n * EMAX + pos] = e;
        }
        cnt += __popc(m);
    }
    if (t == 0) g_cnt[n] = cnt > EMAX ? EMAX : cnt;
}

// ------------- W2 fp16 hi/lo split -------------
__global__ void k_w2split(const float* __restrict__ eW2, const float* __restrict__ eb2) {
    int kb = blockIdx.x;
    int l  = blockIdx.y;
    const float* src = (kb < 128) ? (eW2 + ((size_t)l * 128 + kb) * 16384)
                                  : (eb2 + (size_t)l * 16384);
    size_t off = ((size_t)l * 129 + kb) * 16384;
    for (int i = threadIdx.x; i < 16384; i += 256) {
        __half h, lo;
        hsplit(src[i], h, lo);
        g_W2h[off + i] = h;
        g_W2l[off + i] = lo;
    }
}

// ------------- small transpose -------------
__global__ void k_tr3(const float* __restrict__ A, float* __restrict__ B,
                      int L, int R, int C) {
    size_t tot = (size_t)L * R * C;
    for (size_t idx = blockIdx.x * (size_t)blockDim.x + threadIdx.x; idx < tot;
         idx += (size_t)gridDim.x * blockDim.x) {
        int c = (int)(idx % C);
        size_t tmp = idx / C;
        int r = (int)(tmp % R);
        int l = (int)(tmp / R);
        B[((size_t)l * C + c) * R + r] = A[idx];
    }
}

// ------------- atom embedding -------------
__global__ void k_embed(const float* __restrict__ x, const float* __restrict__ W,
                        const float* __restrict__ b, const float* __restrict__ lg,
                        const float* __restrict__ lb) {
    int n = blockIdx.x, t = threadIdx.x;
    __shared__ float sx[AD];
    __shared__ float red[4];
    if (t < AD) sx[t] = x[n * AD + t];
    __syncthreads();
    float acc = b[t];
    for (int a = 0; a < AD; a++) acc += sx[a] * W[a * DD + t];
    float mu  = bsum128(acc, red) * (1.0f / DD);
    float d   = acc - mu;
    float var = bsum128(d * d, red) * (1.0f / DD);
    float y   = d * rsqrtf(var + 1e-5f) * lg[t] + lb[t];
    g_h[n * DD + t] = gelu_f(y);
}

// ------------- edge hidden -------------
__global__ void k_edget(const float* __restrict__ ea, const float* __restrict__ W1,
                        const float* __restrict__ b1) {
    int e = blockIdx.x, t = threadIdx.x;
    __shared__ float sa[BD];
    if (t < BD) sa[t] = ea[e * BD + t];
    __syncthreads();
    float acc = b1[t];
    #pragma unroll
    for (int a = 0; a < BD; a++) acc += sa[a] * W1[a * DD + t];
    g_t[e * DD + t] = gelu_f(acc);
}

// ------------- S build -> fp16 hi/lo -------------
__global__ void __launch_bounds__(128) k_sbuild() {
    int n = blockIdx.x, half = blockIdx.y, t = threadIdx.x;
    __shared__ float st[64];
    float a[64];
    #pragma unroll
    for (int i = 0; i < 64; i++) a[i] = 0.0f;
    float hs = 0.0f;
    int cnt = g_cnt[n];
    for (int m = 0; m < cnt; m++) {
        int e = g_eidx[n * EMAX + m];
        int s = g_src[e];
        float hv = g_h[s * DD + t];
        if (t < 64) st[t] = g_t[e * DD + half * 64 + t];
        __syncthreads();
        #pragma unroll
        for (int i = 0; i < 64; i++) a[i] += st[i] * hv;
        hs += hv;
        __syncthreads();
    }
    size_t base = (size_t)n * KKD + half * 64 * DD;
    #pragma unroll
    for (int i = 0; i < 64; i++) {
        __half h, lo;
        hsplit(a[i], h, lo);
        g_Sh[base + (size_t)i * DD + t] = h;
        g_Sl[base + (size_t)i * DD + t] = lo;
    }
    if (half == 1) {
        __half h, lo;
        hsplit(hs, h, lo);
        g_Sh[(size_t)n * KKD + 16384 + t] = h;
        g_Sl[(size_t)n * KKD + 16384 + t] = lo;
    }
}

// ------------- fp16-pair tensor GEMM with ldmatrix fragment loads -------------
// 512 thr = 16 warps (4x4), warp tile 32x32 = 2x4 mma(m16n8k16), 3 products each.
#define MATB 6144          // bytes per matrix slab: 128 rows * 24 halves * 2
#define BUFB 24576         // bytes per buffer: 4 slabs
__global__ void __launch_bounds__(512) k_hgemm(
    const __half* __restrict__ Ah_, const __half* __restrict__ Al_,
    const __half* __restrict__ Bh_, const __half* __restrict__ Bl_,
    float* __restrict__ Cpart)
{
    __shared__ unsigned short sm[2][4][128][24];    // 49152 B
    int tid = threadIdx.x;
    int wid = tid >> 5, lane = tid & 31;
    int g = lane >> 2, tig = lane & 3;
    int wm = wid & 3, wn = wid >> 2;
    int m0 = blockIdx.x * 128;
    int z = blockIdx.z;
    int zs = z * 64 + (z < 8 ? z : 8);      // 1032 stages: first 8 CTAs take 65
    int ns = 64 + (z < 8 ? 1 : 0);

    int mat = tid >> 7;
    int row = tid & 127;

    uint32 sbase = smem_u32(sm);
    int grp = lane >> 3, l7 = lane & 7;

    uint32 aoffh[2], aoffl[2], boffh[2], boffl[2];
    #pragma unroll
    for (int mt = 0; mt < 2; mt++) {
        uint32 r = wm * 32 + mt * 16 + l7 + ((grp & 1) ? 8 : 0);
        uint32 ko = (grp >> 1) * 16;
        aoffh[mt] = 0 * MATB + r * 48 + ko;
        aoffl[mt] = 1 * MATB + r * 48 + ko;
    }
    #pragma unroll
    for (int p = 0; p < 2; p++) {
        uint32 r = wn * 32 + p * 16 + l7 + ((grp >> 1) ? 8 : 0);
        uint32 ko = (grp & 1) * 16;
        boffh[p] = 2 * MATB + r * 48 + ko;
        boffl[p] = 3 * MATB + r * 48 + ko;
    }

    float accH[2][4][4], accC[2][4][4];
    #pragma unroll
    for (int mt = 0; mt < 2; mt++)
        #pragma unroll
        for (int nt = 0; nt < 4; nt++)
            #pragma unroll
            for (int q = 0; q < 4; q++) { accH[mt][nt][q] = 0.0f; accC[mt][nt][q] = 0.0f; }

    auto gload = [&](int s, uint4& r0, uint4& r1) {
        int kk = (zs + s) * 16;
        const __half* p;
        if (mat == 0)      p = Ah_ + (size_t)(m0 + row) * KKD + kk;
        else if (mat == 1) p = Al_ + (size_t)(m0 + row) * KKD + kk;
        else {
            int kb = kk >> 7, j0 = kk & 127;
            p = (mat == 2 ? Bh_ : Bl_) + (size_t)kb * 16384 + row * 128 + j0;
        }
        r0 = *(const uint4*)p;
        r1 = *(const uint4*)(p + 8);
    };
    auto sstore = [&](int b, uint4 r0, uint4 r1) {
        *(uint4*)&sm[b][mat][row][0] = r0;
        *(uint4*)&sm[b][mat][row][8] = r1;
    };

    { uint4 r0, r1; gload(0, r0, r1); sstore(0, r0, r1); }
    __syncthreads();

    for (int s = 0; s < ns; s++) {
        int cur = s & 1, nxt = cur ^ 1;
        uint4 p0, p1;
        if (s + 1 < ns) gload(s + 1, p0, p1);

        uint32 bo = sbase + (uint32)cur * BUFB;
        uint32 fah[2][4], fal[2][4], fbh[4][2], fbl[4][2];
        ldm_x4(fah[0][0], fah[0][1], fah[0][2], fah[0][3], bo + aoffh[0]);
        ldm_x4(fah[1][0], fah[1][1], fah[1][2], fah[1][3], bo + aoffh[1]);
        ldm_x4(fal[0][0], fal[0][1], fal[0][2], fal[0][3], bo + aoffl[0]);
        ldm_x4(fal[1][0], fal[1][1], fal[1][2], fal[1][3], bo + aoffl[1]);
        ldm_x4(fbh[0][0], fbh[0][1], fbh[1][0], fbh[1][1], bo + boffh[0]);
        ldm_x4(fbh[2][0], fbh[2][1], fbh[3][0], fbh[3][1], bo + boffh[1]);
        ldm_x4(fbl[0][0], fbl[0][1], fbl[1][0], fbl[1][1], bo + boffl[0]);
        ldm_x4(fbl[2][0], fbl[2][1], fbl[3][0], fbl[3][1], bo + boffl[1]);

        #pragma unroll
        for (int mt = 0; mt < 2; mt++)
            #pragma unroll
            for (int nt = 0; nt < 4; nt++) {
                mma_f16(accH[mt][nt], fah[mt], fbh[nt]);
                mma_f16(accC[mt][nt], fah[mt], fbl[nt]);
                mma_f16(accC[mt][nt], fal[mt], fbh[nt]);
            }

        if (s + 1 < ns) sstore(nxt, p0, p1);
        __syncthreads();
    }

    const float is = 1.0f / 2048.0f;
    float* Co = Cpart + (size_t)z * NN * DD;
    #pragma unroll
    for (int mt = 0; mt < 2; mt++)
        #pragma unroll
        for (int nt = 0; nt < 4; nt++) {
            int r = m0 + wm * 32 + mt * 16 + g;
            int cc = wn * 32 + nt * 8 + 2 * tig;
            float2 o0 = make_float2(accH[mt][nt][0] + accC[mt][nt][0] * is,
                                    accH[mt][nt][1] + accC[mt][nt][1] * is);
            float2 o1 = make_float2(accH[mt][nt][2] + accC[mt][nt][2] * is,
                                    accH[mt][nt][3] + accC[mt][nt][3] * is);
            *(float2*)&Co[(size_t)r * DD + cc]       = o0;
            *(float2*)&Co[(size_t)(r + 8) * DD + cc] = o1;
        }
}

// ------------- fused small GEMMs (reduce folded into z=0 A-load) -------------
// z=0: gi = (sum_q part[q]) @ WihT ; z=1: gh = h @ WhhT
__global__ void __launch_bounds__(256, 2) k_gemm2(
    const float* __restrict__ Apart, const float* __restrict__ A1,
    const float* __restrict__ B0, const float* __restrict__ B1,
    float* __restrict__ C0, float* __restrict__ C1)
{
    int bz = blockIdx.z;
    const float* B = bz ? B1 : B0;
    float* C       = bz ? C1 : C0;
    const int lda = 128, ldb = 384, ldc = 384, Klen = 128;

    __shared__ float As[2][8][132];
    __shared__ float Bs[2][8][128];
    int tid = threadIdx.x;
    int w = tid >> 5, l = tid & 31;
    int wm = w & 3, wn = w >> 2;
    int lm = l & 3, ln = l >> 2;
    int row = wm * 32 + lm * 8;
    int col = wn * 64 + ln * 8;
    int m0 = blockIdx.x * 128, n0 = blockIdx.y * 128;

    int am = tid >> 1, ak = (tid & 1) * 4;
    int bk = tid >> 5, bn = (tid & 31) * 4;

    const float* Aptr = (bz ? A1 : Apart) + (size_t)(m0 + am) * lda + ak;
    const float* Bptr = B + (size_t)bk * ldb + n0 + bn;

    auto loadA = [&](int tt) -> float4 {
        const float* p = Aptr + tt * 8;
        float4 v = *(const float4*)p;
        if (bz == 0) {
            #pragma unroll
            for (int q = 1; q < HSPL; q++) {
                float4 x = *(const float4*)(p + (size_t)q * (NN * DD));
                v.x += x.x; v.y += x.y; v.z += x.z; v.w += x.w;
            }
        }
        return v;
    };

    ull acc[8][4];
    #pragma unroll
    for (int mm = 0; mm < 8; mm++)
        #pragma unroll
        for (int nn = 0; nn < 4; nn++) acc[mm][nn] = 0ull;

    int ntiles = Klen >> 3;
    float4 ra = loadA(0);
    float4 rb = *(const float4*)Bptr;
    As[0][ak + 0][am] = ra.x; As[0][ak + 1][am] = ra.y;
    As[0][ak + 2][am] = ra.z; As[0][ak + 3][am] = ra.w;
    *(float4*)&Bs[0][bk][bn] = rb;
    __syncthreads();

    for (int t = 0; t < ntiles; t++) {
        int cur = t & 1, nxt = cur ^ 1;
        if (t + 1 < ntiles) {
            ra = loadA(t + 1);
            rb = *(const float4*)(Bptr + (size_t)(t + 1) * 8 * ldb);
        }
        #pragma unroll
        for (int kk = 0; kk < 8; kk++) {
            float4 a0 = *(float4*)&As[cur][kk][row];
            float4 a1 = *(float4*)&As[cur][kk][row + 4];
            float4 b0 = *(float4*)&Bs[cur][kk][col];
            float4 b1 = *(float4*)&Bs[cur][kk][col + 4];
            ull bp0 = pk2(b0.x, b0.y), bp1 = pk2(b0.z, b0.w);
            ull bp2 = pk2(b1.x, b1.y), bp3 = pk2(b1.z, b1.w);
            float av[8] = {a0.x, a0.y, a0.z, a0.w, a1.x, a1.y, a1.z, a1.w};
            #pragma unroll
            for (int mm = 0; mm < 8; mm++) {
                ull ap = pk2(av[mm], av[mm]);
                ffma2(acc[mm][0], ap, bp0);
                ffma2(acc[mm][1], ap, bp1);
                ffma2(acc[mm][2], ap, bp2);
                ffma2(acc[mm][3], ap, bp3);
            }
        }
        if (t + 1 < ntiles) {
            As[nxt][ak + 0][am] = ra.x; As[nxt][ak + 1][am] = ra.y;
            As[nxt][ak + 2][am] = ra.z; As[nxt][ak + 3][am] = ra.w;
            *(float4*)&Bs[nxt][bk][bn] = rb;
        }
        __syncthreads();
    }

    #pragma unroll
    for (int mm = 0; mm < 8; mm++) {
        float4 o0, o1;
        upk2(acc[mm][0], o0.x, o0.y); upk2(acc[mm][1], o0.z, o0.w);
        upk2(acc[mm][2], o1.x, o1.y); upk2(acc[mm][3], o1.z, o1.w);
        size_t baseo = (size_t)(m0 + row + mm) * ldc + n0 + col;
        *(float4*)&C[baseo]     = o0;
        *(float4*)&C[baseo + 4] = o1;
    }
}

// ------------- GRU elementwise + LN + residual -------------
__global__ void k_gru(const float* __restrict__ bih, const float* __restrict__ bhh,
                      const float* __restrict__ lg, const float* __restrict__ lb) {
    int n = blockIdx.x, t = threadIdx.x;
    __shared__ float red[4];
    float ir  = g_gi[n * 384 + t]       + bih[t];
    float iz  = g_gi[n * 384 + 128 + t] + bih[128 + t];
    float inn = g_gi[n * 384 + 256 + t] + bih[256 + t];
    float hr  = g_gh[n * 384 + t]       + bhh[t];
    float hz  = g_gh[n * 384 + 128 + t] + bhh[128 + t];
    float hn  = g_gh[n * 384 + 256 + t] + bhh[256 + t];
    float r = sigm(ir + hr);
    float z = sigm(iz + hz);
    float nn = tanhf(inn + r * hn);
    float hold = g_h[n * DD + t];
    float hnew = (1.0f - z) * nn + z * hold;
    float mu  = bsum128(hnew, red) * (1.0f / DD);
    float d   = hnew - mu;
    float var = bsum128(d * d, red) * (1.0f / DD);
    g_h[n * DD + t] = d * rsqrtf(var + 1e-5f) * lg[t] + lb[t] + hold;
}

// ------------- Set2Set + shared MLP + heads -------------
__global__ void __launch_bounds__(128) k_s2s(
    const float* __restrict__ lbih, const float* __restrict__ lbhh,
    const float* __restrict__ Wsh, const float* __restrict__ bsh,
    const float* __restrict__ Whd, const float* __restrict__ bhd,
    float* __restrict__ out)
{
    int g = blockIdx.x, t = threadIdx.x;
    __shared__ float hl[64 * 129];
    __shared__ float hg[128], cg[128], ro[128], sc[64], w_s[64];
    __shared__ float qs[256], sh2[128];
    for (int q = t; q < 64 * 128; q += 128) {
        int nn = q >> 7, i = q & 127;
        hl[nn * 129 + i] = g_h[(g * 64 + nn) * 128 + i];
    }
    hg[t] = 0.0f; cg[t] = 0.0f;
    __syncthreads();

    for (int it = 0; it < 6; it++) {
        if (t < 64) {
            float s = 0.0f;
            for (int i = 0; i < 128; i++) s += hl[t * 129 + i] * hg[i];
            sc[t] = s;
        }
        __syncthreads();
        if (t == 0) {
            float m = 0.0f;
            for (int nn = 0; nn < 64; nn++) m = fmaxf(m, sc[nn]);
            float ss = 0.0f;
            for (int nn = 0; nn < 64; nn++) { float e = expf(sc[nn] - m); w_s[nn] = e; ss += e; }
            float inv = 1.0f / (ss + 1e-8f);
            for (int nn = 0; nn < 64; nn++) w_s[nn] *= inv;
        }
        __syncthreads();
        {
            float r = 0.0f;
            for (int nn = 0; nn < 64; nn++) r += hl[nn * 129 + t] * w_s[nn];
            ro[t] = r;
        }
        __syncthreads();
        float ga[4];
        #pragma unroll
        for (int qg = 0; qg < 4; qg++) ga[qg] = lbih[qg * 128 + t] + lbhh[qg * 128 + t];
        for (int j = 0; j < 128; j++) {
            float rj = ro[j], hj = hg[j];
            #pragma unroll
            for (int qg = 0; qg < 4; qg++)
                ga[qg] += rj * g_lWihT[j * 512 + qg * 128 + t]
                        + hj * g_lWhhT[j * 512 + qg * 128 + t];
        }
        float cn = sigm(ga[1]) * cg[t] + sigm(ga[0]) * tanhf(ga[2]);
        float hn = sigm(ga[3]) * tanhf(cn);
        __syncthreads();
        hg[t] = hn; cg[t] = cn;
        __syncthreads();
    }
    qs[t] = hg[t]; qs[128 + t] = ro[t];
    __syncthreads();
    float acc = bsh[t];
    for (int j = 0; j < 256; j++) acc += qs[j] * Wsh[j * 128 + t];
    sh2[t] = gelu_f(acc);
    __syncthreads();
    if (t < NT) {
        float o = bhd[t];
        for (int i = 0; i < 128; i++) o += sh2[i] * Whd[i * NT + t];
        out[g * NT + t] = o;
    }
}

// ------------- launch -------------
extern "C" void kernel_launch(void* const* d_in, const int* in_sizes, int n_in,
                              void* d_out, int out_size) {
    const float* x        = (const float*)d_in[0];
    const int*   ei       = (const int*)  d_in[1];
    const float* ea       = (const float*)d_in[2];
    const float* W_embed  = (const float*)d_in[4];
    const float* b_embed  = (const float*)d_in[5];
    const float* ln_eg    = (const float*)d_in[6];
    const float* ln_eb    = (const float*)d_in[7];
    const float* eW1      = (const float*)d_in[8];
    const float* eb1      = (const float*)d_in[9];
    const float* eW2      = (const float*)d_in[10];
    const float* eb2      = (const float*)d_in[11];
    const float* gWih     = (const float*)d_in[12];
    const float* gWhh     = (const float*)d_in[13];
    const float* gbih     = (const float*)d_in[14];
    const float* gbhh     = (const float*)d_in[15];
    const float* lng      = (const float*)d_in[16];
    const float* lnb      = (const float*)d_in[17];
    const float* lWih     = (const float*)d_in[18];
    const float* lWhh     = (const float*)d_in[19];
    const float* lbih     = (const float*)d_in[20];
    const float* lbhh     = (const float*)d_in[21];
    const float* Wsh      = (const float*)d_in[22];
    const float* bsh      = (const float*)d_in[23];
    const float* Whd      = (const float*)d_in[24];
    const float* bhd      = (const float*)d_in[25];
    float* out = (float*)d_out;

    __half* dSh;  cudaGetSymbolAddress((void**)&dSh, g_Sh);
    __half* dSl;  cudaGetSymbolAddress((void**)&dSl, g_Sl);
    __half* dW2h; cudaGetSymbolAddress((void**)&dW2h, g_W2h);
    __half* dW2l; cudaGetSymbolAddress((void**)&dW2l, g_W2l);
    float* dWihT; cudaGetSymbolAddress((void**)&dWihT, g_WihT);
    float* dWhhT; cudaGetSymbolAddress((void**)&dWhhT, g_WhhT);
    float* dlWihT; cudaGetSymbolAddress((void**)&dlWihT, g_lWihT);
    float* dlWhhT; cudaGetSymbolAddress((void**)&dlWhhT, g_lWhhT);
    float* dPart; cudaGetSymbolAddress((void**)&dPart, g_part);
    float* dGi;   cudaGetSymbolAddress((void**)&dGi, g_gi);
    float* dGh;   cudaGetSymbolAddress((void**)&dGh, g_gh);
    float* dH;    cudaGetSymbolAddress((void**)&dH, g_h);

    // launches 1-5: prep, embed, w2split, edget, sbuild -> #6 is k_hgemm (ncu -s 5 -c 1)
    k_prep<<<NN, 32>>>(ei);
    k_embed<<<NN, 128>>>(x, W_embed, b_embed, ln_eg, ln_eb);
    k_w2split<<<dim3(129, NL), 256>>>(eW2, eb2);

    for (int l = 0; l < NL; l++) {
        k_edget<<<NE, 128>>>(ea, eW1 + (size_t)l * BD * DD, eb1 + l * DD);
        k_sbuild<<<dim3(NN, 2), 128>>>();
        k_hgemm<<<dim3(16, 1, HSPL), 512>>>(
            dSh, dSl,
            dW2h + (size_t)l * 129 * 16384,
            dW2l + (size_t)l * 129 * 16384,
            dPart);
        if (l == 0) {
            k_tr3<<<256, 256>>>(gWih, dWihT, NL, 384, 128);
            k_tr3<<<256, 256>>>(gWhh, dWhhT, NL, 384, 128);
            k_tr3<<<64, 256>>>(lWih, dlWihT, 1, 512, 128);
            k_tr3<<<64, 256>>>(lWhh, dlWhhT, 1, 512, 128);
        }
        k_gemm2<<<dim3(16, 3, 2), 256>>>(dPart, dH,
                                         dWihT + (size_t)l * 128 * 384,
                                         dWhhT + (size_t)l * 128 * 384,
                                         dGi, dGh);
        k_gru<<<NN, 128>>>(gbih + l * 384, gbhh + l * 384, lng + l * DD, lnb + l * DD);
    }
    k_s2s<<<NG, 128>>>(lbih, lbhh, Wsh, bsh, Whd, bhd, out);
}

// round 15
// speedup vs baseline: 1.2764x; 1.2764x over previous
#include <cuda_runtime.h>
#include <cuda_fp16.h>
#include <cstdint>

#define NN   2048
#define NE   4096
#define NG   32
#define AD   79
#define BD   12
#define DD   128
#define NL   6
#define NT   6
#define KKD  16512          // 128*128 + 128 bias rows
#define EMAX 96
#define HSPL 9              // split-K CTAs: 516 stages of K=32 (first 3 CTAs take 58, rest 57)

typedef unsigned long long ull;
typedef unsigned int uint32;

// ------------- static scratch (no allocations allowed) -------------
__device__ float  g_h[NN * DD];
__device__ float  g_t[NE * DD];
__device__ __half g_Sh[(size_t)NN * KKD];
__device__ __half g_Sl[(size_t)NN * KKD];
__device__ __half g_W2h[(size_t)NL * 129 * 16384];
__device__ __half g_W2l[(size_t)NL * 129 * 16384];
__device__ float  g_part[(size_t)HSPL * NN * DD];
__device__ float  g_agg[NN * DD];
__device__ float  g_gi[NN * 384];
__device__ float  g_gh[NN * 384];
__device__ float  g_WihT[NL * 128 * 384];
__device__ float  g_WhhT[NL * 128 * 384];
__device__ float  g_lWihT[128 * 512];
__device__ float  g_lWhhT[128 * 512];
__device__ int    g_src[NE], g_dst[NE];
__device__ int    g_eidx[NN * EMAX];
__device__ int    g_cnt[NN];

// ------------- helpers -------------
__device__ __forceinline__ float gelu_f(float x) {
    return 0.5f * x * (1.0f + erff(x * 0.70710678f));
}
__device__ __forceinline__ float sigm(float x) { return 1.0f / (1.0f + expf(-x)); }

__device__ __forceinline__ ull pk2(float lo, float hi) {
    ull r; asm("mov.b64 %0, {%1, %2};" : "=l"(r) : "f"(lo), "f"(hi)); return r;
}
__device__ __forceinline__ void upk2(ull v, float& lo, float& hi) {
    asm("mov.b64 {%0, %1}, %2;" : "=f"(lo), "=f"(hi) : "l"(v));
}
__device__ __forceinline__ void ffma2(ull& d, ull a, ull b) {
    asm("fma.rn.f32x2 %0, %1, %2, %0;" : "+l"(d) : "l"(a), "l"(b));
}

__device__ __forceinline__ void mma_f16(float* c, const uint32* a, const uint32* b) {
    asm volatile(
        "mma.sync.aligned.m16n8k16.row.col.f32.f16.f16.f32 "
        "{%0,%1,%2,%3}, {%4,%5,%6,%7}, {%8,%9}, {%0,%1,%2,%3};\n"
        : "+f"(c[0]), "+f"(c[1]), "+f"(c[2]), "+f"(c[3])
        : "r"(a[0]), "r"(a[1]), "r"(a[2]), "r"(a[3]), "r"(b[0]), "r"(b[1]));
}

__device__ __forceinline__ void ldm_x4(uint32& r0, uint32& r1, uint32& r2, uint32& r3,
                                       uint32 addr) {
    asm volatile("ldmatrix.sync.aligned.m8n8.x4.shared.b16 {%0,%1,%2,%3}, [%4];"
                 : "=r"(r0), "=r"(r1), "=r"(r2), "=r"(r3) : "r"(addr));
}

__device__ __forceinline__ uint32 smem_u32(const void* p) {
    uint32 a;
    asm("{ .reg .u64 t; cvta.to.shared.u64 t, %1; cvt.u32.u64 %0, t; }" : "=r"(a) : "l"(p));
    return a;
}

__device__ __forceinline__ void cp16(uint32 d, const void* s) {
    asm volatile("cp.async.cg.shared.global [%0], [%1], 16;" :: "r"(d), "l"(s) : "memory");
}
#define CP_COMMIT() asm volatile("cp.async.commit_group;" ::: "memory")
#define CP_WAIT0()  asm volatile("cp.async.wait_group 0;" ::: "memory")

__device__ __forceinline__ float bsum128(float v, float* red) {
    #pragma unroll
    for (int o = 16; o > 0; o >>= 1) v += __shfl_down_sync(0xffffffffu, v, o);
    if ((threadIdx.x & 31) == 0) red[threadIdx.x >> 5] = v;
    __syncthreads();
    float r = red[0] + red[1] + red[2] + red[3];
    __syncthreads();
    return r;
}

__device__ __forceinline__ void hsplit(float v, __half& h, __half& l) {
    h = __float2half_rn(v);
    l = __float2half_rn((v - __half2float(h)) * 2048.0f);
}

// ------------- prep -------------
__global__ void k_prep(const int* __restrict__ ei) {
    int n = blockIdx.x, t = threadIdx.x;
    bool my64 = true;
    for (int i = t; i < 128; i += 32)
        if (ei[2 * i + 1] != 0) my64 = false;
    bool is64 = __all_sync(0xffffffffu, my64);
    if (t < 2) {
        int e = n * 2 + t;
        g_src[e] = is64 ? ei[2 * e]        : ei[e];
        g_dst[e] = is64 ? ei[2 * (NE + e)] : ei[NE + e];
    }
    int cnt = 0;
    for (int base = 0; base < NE; base += 32) {
        int e = base + t;
        int dv = is64 ? ei[2 * (NE + e)] : ei[NE + e];
        bool ok = (dv == n);
        unsigned m = __ballot_sync(0xffffffffu, ok);
        if (ok) {
            int pos = cnt + __popc(m & ((1u << t) - 1u));
            if (pos < EMAX) g_eidx[n * EMAX + pos] = e;
        }
        cnt += __popc(m);
    }
    if (t == 0) g_cnt[n] = cnt > EMAX ? EMAX : cnt;
}

// ------------- W2 fp16 hi/lo split -------------
__global__ void k_w2split(const float* __restrict__ eW2, const float* __restrict__ eb2) {
    int kb = blockIdx.x;
    int l  = blockIdx.y;
    const float* src = (kb < 128) ? (eW2 + ((size_t)l * 128 + kb) * 16384)
                                  : (eb2 + (size_t)l * 16384);
    size_t off = ((size_t)l * 129 + kb) * 16384;
    for (int i = threadIdx.x; i < 16384; i += 256) {
        __half h, lo;
        hsplit(src[i], h, lo);
        g_W2h[off + i] = h;
        g_W2l[off + i] = lo;
    }
}

// ------------- small transpose -------------
__global__ void k_tr3(const float* __restrict__ A, float* __restrict__ B,
                      int L, int R, int C) {
    size_t tot = (size_t)L * R * C;
    for (size_t idx = blockIdx.x * (size_t)blockDim.x + threadIdx.x; idx < tot;
         idx += (size_t)gridDim.x * blockDim.x) {
        int c = (int)(idx % C);
        size_t tmp = idx / C;
        int r = (int)(tmp % R);
        int l = (int)(tmp / R);
        B[((size_t)l * C + c) * R + r] = A[idx];
    }
}

// ------------- atom embedding -------------
__global__ void k_embed(const float* __restrict__ x, const float* __restrict__ W,
                        const float* __restrict__ b, const float* __restrict__ lg,
                        const float* __restrict__ lb) {
    int n = blockIdx.x, t = threadIdx.x;
    __shared__ float sx[AD];
    __shared__ float red[4];
    if (t < AD) sx[t] = x[n * AD + t];
    __syncthreads();
    float acc = b[t];
    for (int a = 0; a < AD; a++) acc += sx[a] * W[a * DD + t];
    float mu  = bsum128(acc, red) * (1.0f / DD);
    float d   = acc - mu;
    float var = bsum128(d * d, red) * (1.0f / DD);
    float y   = d * rsqrtf(var + 1e-5f) * lg[t] + lb[t];
    g_h[n * DD + t] = gelu_f(y);
}

// ------------- edge hidden -------------
__global__ void k_edget(const float* __restrict__ ea, const float* __restrict__ W1,
                        const float* __restrict__ b1) {
    int e = blockIdx.x, t = threadIdx.x;
    __shared__ float sa[BD];
    if (t < BD) sa[t] = ea[e * BD + t];
    __syncthreads();
    float acc = b1[t];
    #pragma unroll
    for (int a = 0; a < BD; a++) acc += sa[a] * W1[a * DD + t];
    g_t[e * DD + t] = gelu_f(acc);
}

// ------------- S build -> fp16 hi/lo -------------
__global__ void __launch_bounds__(128) k_sbuild() {
    int n = blockIdx.x, half = blockIdx.y, t = threadIdx.x;
    __shared__ float st[64];
    float a[64];
    #pragma unroll
    for (int i = 0; i < 64; i++) a[i] = 0.0f;
    float hs = 0.0f;
    int cnt = g_cnt[n];
    for (int m = 0; m < cnt; m++) {
        int e = g_eidx[n * EMAX + m];
        int s = g_src[e];
        float hv = g_h[s * DD + t];
        if (t < 64) st[t] = g_t[e * DD + half * 64 + t];
        __syncthreads();
        #pragma unroll
        for (int i = 0; i < 64; i++) a[i] += st[i] * hv;
        hs += hv;
        __syncthreads();
    }
    size_t base = (size_t)n * KKD + half * 64 * DD;
    #pragma unroll
    for (int i = 0; i < 64; i++) {
        __half h, lo;
        hsplit(a[i], h, lo);
        g_Sh[base + (size_t)i * DD + t] = h;
        g_Sl[base + (size_t)i * DD + t] = lo;
    }
    if (half == 1) {
        __half h, lo;
        hsplit(hs, h, lo);
        g_Sh[(size_t)n * KKD + 16384 + t] = h;
        g_Sl[(size_t)n * KKD + 16384 + t] = lo;
    }
}

// ------------- fp16-pair tensor GEMM: K=32 stages, cp.async, ldmatrix -------------
// 512 thr = 16 warps (4x4), warp tile 32x32 = 2x4 mma(m16n8k16), 3 products each.
#define MATB 10240         // 128 rows * 40 halves * 2 B
#define BUFB 40960         // 4 slabs
#define HG_SMEM 81920      // 2 buffers
__global__ void __launch_bounds__(512) k_hgemm(
    const __half* __restrict__ Ah_, const __half* __restrict__ Al_,
    const __half* __restrict__ Bh_, const __half* __restrict__ Bl_,
    float* __restrict__ Cpart)
{
    extern __shared__ unsigned short sm[];
    int tid = threadIdx.x;
    int wid = tid >> 5, lane = tid & 31;
    int g = lane >> 2, tig = lane & 3;
    int wm = wid & 3, wn = wid >> 2;
    int m0 = blockIdx.x * 128;
    int z = blockIdx.z;
    int zs = z * 57 + (z < 3 ? z : 3);      // 516 stages of 32-K: first 3 CTAs take 58
    int ns = 57 + (z < 3 ? 1 : 0);

    int mat = tid >> 7;
    int row = tid & 127;

    uint32 sbase = smem_u32(sm);
    int grp = lane >> 3, l7 = lane & 7;

    // ldmatrix per-lane offsets (buffer-relative, k-half 0; +32 B for k-half 1)
    uint32 aoffh[2], aoffl[2], boffh[2], boffl[2];
    #pragma unroll
    for (int mt = 0; mt < 2; mt++) {
        uint32 r = wm * 32 + mt * 16 + l7 + ((grp & 1) ? 8 : 0);
        uint32 ko = (grp >> 1) * 16;
        aoffh[mt] = 0 * MATB + r * 80 + ko;
        aoffl[mt] = 1 * MATB + r * 80 + ko;
    }
    #pragma unroll
    for (int p = 0; p < 2; p++) {
        uint32 r = wn * 32 + p * 16 + l7 + ((grp >> 1) ? 8 : 0);
        uint32 ko = (grp & 1) * 16;
        boffh[p] = 2 * MATB + r * 80 + ko;
        boffl[p] = 3 * MATB + r * 80 + ko;
    }

    float accH[2][4][4], accC[2][4][4];
    #pragma unroll
    for (int mt = 0; mt < 2; mt++)
        #pragma unroll
        for (int nt = 0; nt < 4; nt++)
            #pragma unroll
            for (int q = 0; q < 4; q++) { accH[mt][nt][q] = 0.0f; accC[mt][nt][q] = 0.0f; }

    auto gprefetch = [&](int s, int buf) {
        int kk = (zs + s) * 32;
        const __half* p;
        if (mat == 0)      p = Ah_ + (size_t)(m0 + row) * KKD + kk;
        else if (mat == 1) p = Al_ + (size_t)(m0 + row) * KKD + kk;
        else {
            int kb = kk >> 7, j0 = kk & 127;
            p = (mat == 2 ? Bh_ : Bl_) + (size_t)kb * 16384 + row * 128 + j0;
        }
        uint32 d = sbase + (uint32)buf * BUFB + (uint32)mat * MATB + (uint32)row * 80;
        cp16(d,      p);
        cp16(d + 16, p + 8);
        cp16(d + 32, p + 16);
        cp16(d + 48, p + 24);
    };

    gprefetch(0, 0);
    CP_COMMIT();
    CP_WAIT0();
    __syncthreads();

    for (int s = 0; s < ns; s++) {
        int cur = s & 1, nxt = cur ^ 1;
        if (s + 1 < ns) { gprefetch(s + 1, nxt); CP_COMMIT(); }

        uint32 bo = sbase + (uint32)cur * BUFB;
        #pragma unroll
        for (int s8 = 0; s8 < 2; s8++) {
            uint32 kofs = (uint32)s8 * 32;
            uint32 fah[2][4], fal[2][4], fbh[4][2], fbl[4][2];
            ldm_x4(fah[0][0], fah[0][1], fah[0][2], fah[0][3], bo + aoffh[0] + kofs);
            ldm_x4(fah[1][0], fah[1][1], fah[1][2], fah[1][3], bo + aoffh[1] + kofs);
            ldm_x4(fal[0][0], fal[0][1], fal[0][2], fal[0][3], bo + aoffl[0] + kofs);
            ldm_x4(fal[1][0], fal[1][1], fal[1][2], fal[1][3], bo + aoffl[1] + kofs);
            ldm_x4(fbh[0][0], fbh[0][1], fbh[1][0], fbh[1][1], bo + boffh[0] + kofs);
            ldm_x4(fbh[2][0], fbh[2][1], fbh[3][0], fbh[3][1], bo + boffh[1] + kofs);
            ldm_x4(fbl[0][0], fbl[0][1], fbl[1][0], fbl[1][1], bo + boffl[0] + kofs);
            ldm_x4(fbl[2][0], fbl[2][1], fbl[3][0], fbl[3][1], bo + boffl[1] + kofs);

            #pragma unroll
            for (int mt = 0; mt < 2; mt++)
                #pragma unroll
                for (int nt = 0; nt < 4; nt++) {
                    mma_f16(accH[mt][nt], fah[mt], fbh[nt]);
                    mma_f16(accC[mt][nt], fah[mt], fbl[nt]);
                    mma_f16(accC[mt][nt], fal[mt], fbh[nt]);
                }
        }
        if (s + 1 < ns) CP_WAIT0();
        __syncthreads();
    }

    const float is = 1.0f / 2048.0f;
    float* Co = Cpart + (size_t)z * NN * DD;
    #pragma unroll
    for (int mt = 0; mt < 2; mt++)
        #pragma unroll
        for (int nt = 0; nt < 4; nt++) {
            int r = m0 + wm * 32 + mt * 16 + g;
            int cc = wn * 32 + nt * 8 + 2 * tig;
            float2 o0 = make_float2(accH[mt][nt][0] + accC[mt][nt][0] * is,
                                    accH[mt][nt][1] + accC[mt][nt][1] * is);
            float2 o1 = make_float2(accH[mt][nt][2] + accC[mt][nt][2] * is,
                                    accH[mt][nt][3] + accC[mt][nt][3] * is);
            *(float2*)&Co[(size_t)r * DD + cc]       = o0;
            *(float2*)&Co[(size_t)(r + 8) * DD + cc] = o1;
        }
}

// ------------- fused small GEMMs: z=0: gi = agg@WihT ; z=1: gh = h@WhhT -------------
__global__ void __launch_bounds__(256, 2) k_gemm2(
    const float* __restrict__ A0, const float* __restrict__ A1,
    const float* __restrict__ B0, const float* __restrict__ B1,
    float* __restrict__ C0, float* __restrict__ C1)
{
    const float* A = blockIdx.z ? A1 : A0;
    const float* B = blockIdx.z ? B1 : B0;
    float* C       = blockIdx.z ? C1 : C0;
    const int lda = 128, ldb = 384, ldc = 384, Klen = 128;

    __shared__ float As[2][8][132];
    __shared__ float Bs[2][8][128];
    int tid = threadIdx.x;
    int w = tid >> 5, l = tid & 31;
    int wm = w & 3, wn = w >> 2;
    int lm = l & 3, ln = l >> 2;
    int row = wm * 32 + lm * 8;
    int col = wn * 64 + ln * 8;
    int m0 = blockIdx.x * 128, n0 = blockIdx.y * 128;

    int am = tid >> 1, ak = (tid & 1) * 4;
    int bk = tid >> 5, bn = (tid & 31) * 4;

    const float* Aptr = A + (size_t)(m0 + am) * lda + ak;
    const float* Bptr = B + (size_t)bk * ldb + n0 + bn;

    ull acc[8][4];
    #pragma unroll
    for (int mm = 0; mm < 8; mm++)
        #pragma unroll
        for (int nn = 0; nn < 4; nn++) acc[mm][nn] = 0ull;

    int ntiles = Klen >> 3;
    float4 ra = *(const float4*)Aptr;
    float4 rb = *(const float4*)Bptr;
    As[0][ak + 0][am] = ra.x; As[0][ak + 1][am] = ra.y;
    As[0][ak + 2][am] = ra.z; As[0][ak + 3][am] = ra.w;
    *(float4*)&Bs[0][bk][bn] = rb;
    __syncthreads();

    for (int t = 0; t < ntiles; t++) {
        int cur = t & 1, nxt = cur ^ 1;
        if (t + 1 < ntiles) {
            ra = *(const float4*)(Aptr + (t + 1) * 8);
            rb = *(const float4*)(Bptr + (size_t)(t + 1) * 8 * ldb);
        }
        #pragma unroll
        for (int kk = 0; kk < 8; kk++) {
            float4 a0 = *(float4*)&As[cur][kk][row];
            float4 a1 = *(float4*)&As[cur][kk][row + 4];
            float4 b0 = *(float4*)&Bs[cur][kk][col];
            float4 b1 = *(float4*)&Bs[cur][kk][col + 4];
            ull bp0 = pk2(b0.x, b0.y), bp1 = pk2(b0.z, b0.w);
            ull bp2 = pk2(b1.x, b1.y), bp3 = pk2(b1.z, b1.w);
            float av[8] = {a0.x, a0.y, a0.z, a0.w, a1.x, a1.y, a1.z, a1.w};
            #pragma unroll
            for (int mm = 0; mm < 8; mm++) {
                ull ap = pk2(av[mm], av[mm]);
                ffma2(acc[mm][0], ap, bp0);
                ffma2(acc[mm][1], ap, bp1);
                ffma2(acc[mm][2], ap, bp2);
                ffma2(acc[mm][3], ap, bp3);
            }
        }
        if (t + 1 < ntiles) {
            As[nxt][ak + 0][am] = ra.x; As[nxt][ak + 1][am] = ra.y;
            As[nxt][ak + 2][am] = ra.z; As[nxt][ak + 3][am] = ra.w;
            *(float4*)&Bs[nxt][bk][bn] = rb;
        }
        __syncthreads();
    }

    #pragma unroll
    for (int mm = 0; mm < 8; mm++) {
        float4 o0, o1;
        upk2(acc[mm][0], o0.x, o0.y); upk2(acc[mm][1], o0.z, o0.w);
        upk2(acc[mm][2], o1.x, o1.y); upk2(acc[mm][3], o1.z, o1.w);
        size_t baseo = (size_t)(m0 + row + mm) * ldc + n0 + col;
        *(float4*)&C[baseo]     = o0;
        *(float4*)&C[baseo + 4] = o1;
    }
}

// ------------- reduce split-K partials (fixed order, float4) -------------
__global__ void k_reduce() {
    int i = blockIdx.x * blockDim.x + threadIdx.x;
    const float4* p = (const float4*)g_part;
    float4 s = {0.f, 0.f, 0.f, 0.f};
    #pragma unroll
    for (int q = 0; q < HSPL; q++) {
        float4 v = p[(size_t)q * (NN * DD / 4) + i];
        s.x += v.x; s.y += v.y; s.z += v.z; s.w += v.w;
    }
    ((float4*)g_agg)[i] = s;
}

// ------------- GRU elementwise + LN + residual -------------
__global__ void k_gru(const float* __restrict__ bih, const float* __restrict__ bhh,
                      const float* __restrict__ lg, const float* __restrict__ lb) {
    int n = blockIdx.x, t = threadIdx.x;
    __shared__ float red[4];
    float ir  = g_gi[n * 384 + t]       + bih[t];
    float iz  = g_gi[n * 384 + 128 + t] + bih[128 + t];
    float inn = g_gi[n * 384 + 256 + t] + bih[256 + t];
    float hr  = g_gh[n * 384 + t]       + bhh[t];
    float hz  = g_gh[n * 384 + 128 + t] + bhh[128 + t];
    float hn  = g_gh[n * 384 + 256 + t] + bhh[256 + t];
    float r = sigm(ir + hr);
    float z = sigm(iz + hz);
    float nn = tanhf(inn + r * hn);
    float hold = g_h[n * DD + t];
    float hnew = (1.0f - z) * nn + z * hold;
    float mu  = bsum128(hnew, red) * (1.0f / DD);
    float d   = hnew - mu;
    float var = bsum128(d * d, red) * (1.0f / DD);
    g_h[n * DD + t] = d * rsqrtf(var + 1e-5f) * lg[t] + lb[t] + hold;
}

// ------------- Set2Set + shared MLP + heads -------------
__global__ void __launch_bounds__(128) k_s2s(
    const float* __restrict__ lbih, const float* __restrict__ lbhh,
    const float* __restrict__ Wsh, const float* __restrict__ bsh,
    const float* __restrict__ Whd, const float* __restrict__ bhd,
    float* __restrict__ out)
{
    int g = blockIdx.x, t = threadIdx.x;
    __shared__ float hl[64 * 129];
    __shared__ float hg[128], cg[128], ro[128], sc[64], w_s[64];
    __shared__ float qs[256], sh2[128];
    for (int q = t; q < 64 * 128; q += 128) {
        int nn = q >> 7, i = q & 127;
        hl[nn * 129 + i] = g_h[(g * 64 + nn) * 128 + i];
    }
    hg[t] = 0.0f; cg[t] = 0.0f;
    __syncthreads();

    for (int it = 0; it < 6; it++) {
        if (t < 64) {
            float s = 0.0f;
            for (int i = 0; i < 128; i++) s += hl[t * 129 + i] * hg[i];
            sc[t] = s;
        }
        __syncthreads();
        if (t == 0) {
            float m = 0.0f;
            for (int nn = 0; nn < 64; nn++) m = fmaxf(m, sc[nn]);
            float ss = 0.0f;
            for (int nn = 0; nn < 64; nn++) { float e = expf(sc[nn] - m); w_s[nn] = e; ss += e; }
            float inv = 1.0f / (ss + 1e-8f);
            for (int nn = 0; nn < 64; nn++) w_s[nn] *= inv;
        }
        __syncthreads();
        {
            float r = 0.0f;
            for (int nn = 0; nn < 64; nn++) r += hl[nn * 129 + t] * w_s[nn];
            ro[t] = r;
        }
        __syncthreads();
        float ga[4];
        #pragma unroll
        for (int qg = 0; qg < 4; qg++) ga[qg] = lbih[qg * 128 + t] + lbhh[qg * 128 + t];
        for (int j = 0; j < 128; j++) {
            float rj = ro[j], hj = hg[j];
            #pragma unroll
            for (int qg = 0; qg < 4; qg++)
                ga[qg] += rj * g_lWihT[j * 512 + qg * 128 + t]
                        + hj * g_lWhhT[j * 512 + qg * 128 + t];
        }
        float cn = sigm(ga[1]) * cg[t] + sigm(ga[0]) * tanhf(ga[2]);
        float hn = sigm(ga[3]) * tanhf(cn);
        __syncthreads();
        hg[t] = hn; cg[t] = cn;
        __syncthreads();
    }
    qs[t] = hg[t]; qs[128 + t] = ro[t];
    __syncthreads();
    float acc = bsh[t];
    for (int j = 0; j < 256; j++) acc += qs[j] * Wsh[j * 128 + t];
    sh2[t] = gelu_f(acc);
    __syncthreads();
    if (t < NT) {
        float o = bhd[t];
        for (int i = 0; i < 128; i++) o += sh2[i] * Whd[i * NT + t];
        out[g * NT + t] = o;
    }
}

// ------------- launch -------------
extern "C" void kernel_launch(void* const* d_in, const int* in_sizes, int n_in,
                              void* d_out, int out_size) {
    const float* x        = (const float*)d_in[0];
    const int*   ei       = (const int*)  d_in[1];
    const float* ea       = (const float*)d_in[2];
    const float* W_embed  = (const float*)d_in[4];
    const float* b_embed  = (const float*)d_in[5];
    const float* ln_eg    = (const float*)d_in[6];
    const float* ln_eb    = (const float*)d_in[7];
    const float* eW1      = (const float*)d_in[8];
    const float* eb1      = (const float*)d_in[9];
    const float* eW2      = (const float*)d_in[10];
    const float* eb2      = (const float*)d_in[11];
    const float* gWih     = (const float*)d_in[12];
    const float* gWhh     = (const float*)d_in[13];
    const float* gbih     = (const float*)d_in[14];
    const float* gbhh     = (const float*)d_in[15];
    const float* lng      = (const float*)d_in[16];
    const float* lnb      = (const float*)d_in[17];
    const float* lWih     = (const float*)d_in[18];
    const float* lWhh     = (const float*)d_in[19];
    const float* lbih     = (const float*)d_in[20];
    const float* lbhh     = (const float*)d_in[21];
    const float* Wsh      = (const float*)d_in[22];
    const float* bsh      = (const float*)d_in[23];
    const float* Whd      = (const float*)d_in[24];
    const float* bhd      = (const float*)d_in[25];
    float* out = (float*)d_out;

    __half* dSh;  cudaGetSymbolAddress((void**)&dSh, g_Sh);
    __half* dSl;  cudaGetSymbolAddress((void**)&dSl, g_Sl);
    __half* dW2h; cudaGetSymbolAddress((void**)&dW2h, g_W2h);
    __half* dW2l; cudaGetSymbolAddress((void**)&dW2l, g_W2l);
    float* dWihT; cudaGetSymbolAddress((void**)&dWihT, g_WihT);
    float* dWhhT; cudaGetSymbolAddress((void**)&dWhhT, g_WhhT);
    float* dlWihT; cudaGetSymbolAddress((void**)&dlWihT, g_lWihT);
    float* dlWhhT; cudaGetSymbolAddress((void**)&dlWhhT, g_lWhhT);
    float* dPart; cudaGetSymbolAddress((void**)&dPart, g_part);
    float* dAgg;  cudaGetSymbolAddress((void**)&dAgg, g_agg);
    float* dGi;   cudaGetSymbolAddress((void**)&dGi, g_gi);
    float* dGh;   cudaGetSymbolAddress((void**)&dGh, g_gh);
    float* dH;    cudaGetSymbolAddress((void**)&dH, g_h);

    cudaFuncSetAttribute(k_hgemm, cudaFuncAttributeMaxDynamicSharedMemorySize, HG_SMEM);

    k_prep<<<NN, 32>>>(ei);
    k_embed<<<NN, 128>>>(x, W_embed, b_embed, ln_eg, ln_eb);
    k_w2split<<<dim3(129, NL), 256>>>(eW2, eb2);

    for (int l = 0; l < NL; l++) {
        k_edget<<<NE, 128>>>(ea, eW1 + (size_t)l * BD * DD, eb1 + l * DD);
        k_sbuild<<<dim3(NN, 2), 128>>>();
        k_hgemm<<<dim3(16, 1, HSPL), 512, HG_SMEM>>>(
            dSh, dSl,
            dW2h + (size_t)l * 129 * 16384,
            dW2l + (size_t)l * 129 * 16384,
            dPart);
        if (l == 0) {
            k_tr3<<<256, 256>>>(gWih, dWihT, NL, 384, 128);
            k_tr3<<<256, 256>>>(gWhh, dWhhT, NL, 384, 128);
            k_tr3<<<64, 256>>>(lWih, dlWihT, 1, 512, 128);
            k_tr3<<<64, 256>>>(lWhh, dlWhhT, 1, 512, 128);
        }
        k_reduce<<<128, 512>>>();
        k_gemm2<<<dim3(16, 3, 2), 256>>>(dAgg, dH,
                                         dWihT + (size_t)l * 128 * 384,
                                         dWhhT + (size_t)l * 128 * 384,
                                         dGi, dGh);
        k_gru<<<NN, 128>>>(gbih + l * 384, gbhh + l * 384, lng + l * DD, lnb + l * DD);
    }
    k_s2s<<<NG, 128>>>(lbih, lbhh, Wsh, bsh, Whd, bhd, out);
}